// round 13
// baseline (speedup 1.0000x reference)
#include <cuda_runtime.h>
#include <cuda_bf16.h>
#include <cuda_fp16.h>
#include <math.h>
#include <float.h>
#include <mma.h>

using namespace nvcuda;

#define NN 50000
#define NE 600000
#define NT (NE + NN)      // edges incl. one self loop per node
#define NB 128
#define DD 128
#define NEG 0.2f

// ---------------- scratch (static device globals; no runtime alloc) -------
__device__ int   g_i64;            // 1 if index inputs are int64, 0 if int32
__device__ int   g_deg[NN];
__device__ int   g_rowptr[NN + 1];
__device__ int   g_cursor[NN];
__device__ int   g_csr[NT];
__device__ float g_z[(NN + 128) * DD];    // padded: gemm tiles store unguarded
__device__ __half g_zh[NN * DD];          // fp16 gather copy of z
__device__ float g_hA[NN * DD];
__device__ float g_hB[NN * DD];
__device__ float g_as[NN * 4];
__device__ float g_ad[NN * 4];
__device__ float g_ex[NT * 4];
__device__ float g_z0[DD];
__device__ float g_gsum[NB * DD];
__device__ int   g_gcnt[NB];
__device__ __nv_bfloat16 g_Whi[2 * DD * DD];
__device__ __nv_bfloat16 g_Wlo[2 * DD * DD];

__device__ __forceinline__ float lrelu(float x) { return x > 0.f ? x : NEG * x; }
__device__ __forceinline__ float elu(float x)   { return x > 0.f ? x : expm1f(x); }

// dtype-agnostic index load (branch on device flag)
__device__ __forceinline__ int ld_idx(const void* p, int i) {
    if (g_i64) return (int)((const long long*)p)[i];
    return ((const int*)p)[i];
}

// fp16 z-row gather: 8 bytes per lane (4 channels)
__device__ __forceinline__ void ld_zh4(int s, int c0, float2& za, float2& zb) {
    uint2 raw = *(const uint2*)&g_zh[s * DD + c0];
    za = __half22float2(*(__half2*)&raw.x);
    zb = __half22float2(*(__half2*)&raw.y);
}

// ---------------- dtype detection (warp ballot over 64 int64 views) ------
__global__ void k_detect(const void* edge) {
    int l = threadIdx.x;
    const long long* e64 = (const long long*)edge;
    long long v0 = e64[l];
    long long v1 = e64[32 + l];
    int bad = (v0 < 0 || v0 >= NN || v1 < 0 || v1 >= NN);
    unsigned m = __ballot_sync(0xffffffffu, bad);
    if (l == 0) g_i64 = (m == 0);   // any out-of-range 64-bit view => int32
}

// ---------------- CSR build (4 edges per thread) ---------------------------
#define EPT 4

__global__ void k_count(const void* __restrict__ edge) {
    int base = (blockIdx.x * blockDim.x + threadIdx.x) * EPT;
    #pragma unroll
    for (int j = 0; j < EPT; j++) {
        int e = base + j;
        if (e < NE) {
            int d = ld_idx(edge, NE + e);
            atomicAdd(&g_deg[d], 1);
        }
    }
}

// single-kernel exclusive scan of (deg+1) + CSR setup.
// Block offset computed directly: sum g_deg[0, b*1024) + b*1024.
__global__ __launch_bounds__(1024)
void k_scan() {
    __shared__ int wsum[32];
    __shared__ int s_boff;
    int b = blockIdx.x, t = threadIdx.x;
    int lane = t & 31, w = t >> 5;

    // ---- block offset (coalesced strided sum) ----
    int pre = 0;
    for (int i = t; i < b * 1024; i += 1024) pre += g_deg[i];
    #pragma unroll
    for (int off = 16; off > 0; off >>= 1)
        pre += __shfl_down_sync(0xffffffffu, pre, off);
    if (lane == 0) wsum[w] = pre;
    __syncthreads();
    if (w == 0) {
        int x = wsum[lane];
        #pragma unroll
        for (int off = 16; off > 0; off >>= 1)
            x += __shfl_down_sync(0xffffffffu, x, off);
        if (lane == 0) s_boff = x + b * 1024;
    }
    __syncthreads();

    // ---- shuffle-based inclusive scan of v = deg+1 within block ----
    int i = b * 1024 + t;
    int v = (i < NN) ? g_deg[i] + 1 : 0;
    int incl = v;
    #pragma unroll
    for (int off = 1; off < 32; off <<= 1) {
        int y = __shfl_up_sync(0xffffffffu, incl, off);
        if (lane >= off) incl += y;
    }
    if (lane == 31) wsum[w] = incl;
    __syncthreads();
    if (w == 0) {
        int x = wsum[lane];
        int sx = x;
        #pragma unroll
        for (int off = 1; off < 32; off <<= 1) {
            int y = __shfl_up_sync(0xffffffffu, sx, off);
            if (lane >= off) sx += y;
        }
        wsum[lane] = sx - x;                       // exclusive warp offsets
    }
    __syncthreads();
    incl += wsum[w];
    int boff = s_boff;
    if (i < NN) {
        int r = boff + incl - v;                   // exclusive
        g_rowptr[i] = r;
        g_csr[r] = i;                              // self loop first
        g_cursor[i] = r + 1;
        if (i == NN - 1) g_rowptr[NN] = boff + incl;
    }
}

__global__ void k_scatter(const void* __restrict__ edge) {
    int base = (blockIdx.x * blockDim.x + threadIdx.x) * EPT;
    int d[EPT], s[EPT];
    #pragma unroll
    for (int j = 0; j < EPT; j++) {
        int e = base + j;
        if (e < NE) {
            d[j] = ld_idx(edge, NE + e);
            s[j] = ld_idx(edge, e);
        } else d[j] = -1;
    }
    int pos[EPT];
    #pragma unroll
    for (int j = 0; j < EPT; j++)                 // independent atomic chains
        if (d[j] >= 0) pos[j] = atomicAdd(&g_cursor[d[j]], 1);
    #pragma unroll
    for (int j = 0; j < EPT; j++)
        if (d[j] >= 0) g_csr[pos[j]] = s[j];
}

// ---------------- W split (bf16 hi/lo, both conv layers) ------------------
__global__ void k_wsplit(const float* __restrict__ lin_w) {
    int i = blockIdx.x * blockDim.x + threadIdx.x;
    if (i < 2 * DD * DD) {
        float w = lin_w[DD * DD + i];             // layers 1 and 2
        __nv_bfloat16 hi = __float2bfloat16_rn(w);
        g_Whi[i] = hi;
        g_Wlo[i] = __float2bfloat16_rn(w - __bfloat162float(hi));
    }
}

// ---------------- layer 1 (degenerate: all input rows identical) ----------
__global__ void k_z0(const float* __restrict__ emb, const float* __restrict__ W0) {
    int j = threadIdx.x;
    float s = 0.f;
    for (int k = 0; k < DD; k++) s += emb[k] * W0[k * DD + j];
    g_z0[j] = s;
}

__global__ void k_layer1(const float* __restrict__ emb) {
    int gid = blockIdx.x * blockDim.x + threadIdx.x;
    int n = gid >> 5;
    if (n >= NN) return;
    int c0 = (gid & 31) * 4;
    float scale = 1.0f + (float)(g_rowptr[n + 1] - g_rowptr[n]);
    float4 z = *(const float4*)&g_z0[c0];
    float4 e = *(const float4*)&emb[c0];
    float4 o;
    o.x = elu(z.x * scale) + e.x;
    o.y = elu(z.y * scale) + e.y;
    o.z = elu(z.z * scale) + e.z;
    o.w = elu(z.w * scale) + e.w;
    *(float4*)&g_hA[n * DD + c0] = o;
}

// ---------------- GEMM  z = H @ W  (split-bf16 x3, ~fp22 accuracy) --------
__global__ __launch_bounds__(256)
void k_gemm(int layer, int inB) {
    const float* __restrict__ A = inB ? g_hB : g_hA;
    const __nv_bfloat16* __restrict__ WH = g_Whi + layer * DD * DD;
    const __nv_bfloat16* __restrict__ WL = g_Wlo + layer * DD * DD;
    __shared__ __nv_bfloat16 Ahi[128][40];        // stride 40 elems = 80B (16B mult)
    __shared__ __nv_bfloat16 Alo[128][40];
    __shared__ __nv_bfloat16 Bhi[32][136];        // stride 136 elems = 272B (16B mult)
    __shared__ __nv_bfloat16 Blo[32][136];
    int tid = threadIdx.x;
    int wid = tid >> 5;
    int wr = wid >> 1;                            // 0..3 (row group of 32)
    int wc = wid & 1;                             // 0..1 (col group of 64)
    int row0 = blockIdx.x * 128;

    wmma::fragment<wmma::accumulator, 16, 16, 16, float> c[2][4];
    #pragma unroll
    for (int i = 0; i < 2; i++)
        #pragma unroll
        for (int j = 0; j < 4; j++) wmma::fill_fragment(c[i][j], 0.0f);

    for (int kt = 0; kt < 4; kt++) {
        int k0 = kt * 32;
        #pragma unroll
        for (int i = 0; i < 4; i++) {             // A tile: 128x32 fp32 -> bf16 hi/lo
            int idx = tid + i * 256;
            int r = idx >> 3, kq = idx & 7;
            float4 v = make_float4(0.f, 0.f, 0.f, 0.f);
            int gr = row0 + r;
            if (gr < NN) v = *(const float4*)&A[gr * DD + k0 + kq * 4];
            __nv_bfloat16 hx = __float2bfloat16_rn(v.x);
            __nv_bfloat16 hy = __float2bfloat16_rn(v.y);
            __nv_bfloat16 hz = __float2bfloat16_rn(v.z);
            __nv_bfloat16 hw = __float2bfloat16_rn(v.w);
            __nv_bfloat162* ph = (__nv_bfloat162*)&Ahi[r][kq * 4];
            ph[0] = __nv_bfloat162(hx, hy);
            ph[1] = __nv_bfloat162(hz, hw);
            __nv_bfloat162* pl = (__nv_bfloat162*)&Alo[r][kq * 4];
            pl[0] = __nv_bfloat162(__float2bfloat16_rn(v.x - __bfloat162float(hx)),
                                   __float2bfloat16_rn(v.y - __bfloat162float(hy)));
            pl[1] = __nv_bfloat162(__float2bfloat16_rn(v.z - __bfloat162float(hz)),
                                   __float2bfloat16_rn(v.w - __bfloat162float(hw)));
        }
        #pragma unroll
        for (int i = 0; i < 2; i++) {             // B tiles: 32x128 bf16 (presplit)
            int idx = tid + i * 256;              // 0..511
            int k = idx >> 4, q = idx & 15;       // q-th group of 8 bf16
            *(uint4*)&Bhi[k][q * 8] = *(const uint4*)&WH[(k0 + k) * DD + q * 8];
            *(uint4*)&Blo[k][q * 8] = *(const uint4*)&WL[(k0 + k) * DD + q * 8];
        }
        __syncthreads();
        #pragma unroll
        for (int ks = 0; ks < 2; ks++) {          // 2 k-steps of 16
            wmma::fragment<wmma::matrix_a, 16, 16, 16, __nv_bfloat16, wmma::row_major> ah[2], al[2];
            #pragma unroll
            for (int i = 0; i < 2; i++) {
                wmma::load_matrix_sync(ah[i], &Ahi[wr * 32 + i * 16][ks * 16], 40);
                wmma::load_matrix_sync(al[i], &Alo[wr * 32 + i * 16][ks * 16], 40);
            }
            #pragma unroll
            for (int j = 0; j < 4; j++) {
                wmma::fragment<wmma::matrix_b, 16, 16, 16, __nv_bfloat16, wmma::row_major> bh, bl;
                wmma::load_matrix_sync(bh, &Bhi[ks * 16][wc * 64 + j * 16], 136);
                wmma::load_matrix_sync(bl, &Blo[ks * 16][wc * 64 + j * 16], 136);
                #pragma unroll
                for (int i = 0; i < 2; i++) {
                    wmma::mma_sync(c[i][j], al[i], bh, c[i][j]);   // lo*hi
                    wmma::mma_sync(c[i][j], ah[i], bl, c[i][j]);   // hi*lo
                    wmma::mma_sync(c[i][j], ah[i], bh, c[i][j]);   // hi*hi
                }
            }
        }
        __syncthreads();
    }
    // store (g_z padded by 128 rows: unguarded OK)
    #pragma unroll
    for (int i = 0; i < 2; i++)
        #pragma unroll
        for (int j = 0; j < 4; j++) {
            int gr = row0 + wr * 32 + i * 16;
            int gcol = wc * 64 + j * 16;
            wmma::store_matrix_sync(&g_z[gr * DD + gcol], c[i][j], DD, wmma::mem_row_major);
        }
}

// ---------------- attention coefficients + fp16 z copy --------------------
__global__ void k_coef(const float* __restrict__ att_s, const float* __restrict__ att_d) {
    int gid = blockIdx.x * blockDim.x + threadIdx.x;
    int n = gid >> 5;
    if (n >= NN) return;
    int l = gid & 31;
    int c0 = 4 * l;
    int h = l >> 3;
    int d0 = c0 & 31;
    float4 zv = *(const float4*)&g_z[n * DD + c0];
    // fp16 gather copy (used by k_edge phase 3)
    __half2 hz0 = __floats2half2_rn(zv.x, zv.y);
    __half2 hz1 = __floats2half2_rn(zv.z, zv.w);
    uint2 raw;
    raw.x = *(unsigned*)&hz0;
    raw.y = *(unsigned*)&hz1;
    *(uint2*)&g_zh[n * DD + c0] = raw;
    const float* sv = att_s + h * 32 + d0;
    const float* dv = att_d + h * 32 + d0;
    float ps = zv.x * sv[0] + zv.y * sv[1] + zv.z * sv[2] + zv.w * sv[3];
    float pd = zv.x * dv[0] + zv.y * dv[1] + zv.z * dv[2] + zv.w * dv[3];
    #pragma unroll
    for (int off = 1; off <= 4; off <<= 1) {
        ps += __shfl_xor_sync(0xffffffffu, ps, off);
        pd += __shfl_xor_sync(0xffffffffu, pd, off);
    }
    if ((l & 7) == 0) {
        g_as[n * 4 + h] = ps;
        g_ad[n * 4 + h] = pd;
    }
}

// ---------------- fused edge softmax + aggregation + ELU + residual ------
__global__ __launch_bounds__(256)
void k_edge(int inB) {
    const float* __restrict__ h_in = inB ? g_hB : g_hA;
    float* __restrict__ h_out      = inB ? g_hA : g_hB;
    __shared__ float s_ex[8][32 * 4];             // per-warp [edge][head]
    int gid = blockIdx.x * blockDim.x + threadIdx.x;
    int n = gid >> 5;
    if (n >= NN) return;
    int l = gid & 31;
    int ww = (threadIdx.x >> 5);
    int start = g_rowptr[n], end = g_rowptr[n + 1];
    int deg = end - start;
    float ad0 = g_ad[n * 4 + 0], ad1 = g_ad[n * 4 + 1];
    float ad2 = g_ad[n * 4 + 2], ad3 = g_ad[n * 4 + 3];
    int hd = l >> 3;
    int c0 = 4 * l;
    float invden;

    if (deg <= 32) {
        // ---- fast path: one edge per lane ----
        int sidx = 0;
        float a0 = -FLT_MAX, a1 = -FLT_MAX, a2 = -FLT_MAX, a3 = -FLT_MAX;
        if (l < deg) {
            sidx = g_csr[start + l];
            float4 as = *(const float4*)&g_as[sidx * 4];
            a0 = lrelu(as.x + ad0); a1 = lrelu(as.y + ad1);
            a2 = lrelu(as.z + ad2); a3 = lrelu(as.w + ad3);
        }
        float m0 = a0, m1 = a1, m2 = a2, m3 = a3;
        #pragma unroll
        for (int off = 16; off > 0; off >>= 1) {
            m0 = fmaxf(m0, __shfl_xor_sync(0xffffffffu, m0, off));
            m1 = fmaxf(m1, __shfl_xor_sync(0xffffffffu, m1, off));
            m2 = fmaxf(m2, __shfl_xor_sync(0xffffffffu, m2, off));
            m3 = fmaxf(m3, __shfl_xor_sync(0xffffffffu, m3, off));
        }
        float e0 = 0.f, e1 = 0.f, e2 = 0.f, e3 = 0.f;
        if (l < deg) {
            e0 = expf(a0 - m0); e1 = expf(a1 - m1);
            e2 = expf(a2 - m2); e3 = expf(a3 - m3);
            *(float4*)&s_ex[ww][l * 4] = make_float4(e0, e1, e2, e3);
        }
        float d0 = e0, d1 = e1, d2 = e2, d3 = e3;
        #pragma unroll
        for (int off = 16; off > 0; off >>= 1) {
            d0 += __shfl_xor_sync(0xffffffffu, d0, off);
            d1 += __shfl_xor_sync(0xffffffffu, d1, off);
            d2 += __shfl_xor_sync(0xffffffffu, d2, off);
            d3 += __shfl_xor_sync(0xffffffffu, d3, off);
        }
        __syncwarp();
        float den = hd == 0 ? d0 : hd == 1 ? d1 : hd == 2 ? d2 : d3;
        invden = 1.0f / den;
        float4 acc = make_float4(0.f, 0.f, 0.f, 0.f);
        for (int e = 0; e < deg; e++) {
            int s = __shfl_sync(0xffffffffu, sidx, e);
            float w = s_ex[ww][e * 4 + hd] * invden + 1.0f;
            float2 za, zb;
            ld_zh4(s, c0, za, zb);
            acc.x += w * za.x; acc.y += w * za.y;
            acc.z += w * zb.x; acc.w += w * zb.y;
        }
        float4 hv = *(const float4*)&h_in[n * DD + c0];
        float4 o;
        o.x = elu(acc.x) + hv.x;
        o.y = elu(acc.y) + hv.y;
        o.z = elu(acc.z) + hv.z;
        o.w = elu(acc.w) + hv.w;
        *(float4*)&h_out[n * DD + c0] = o;
        return;
    }

    // ---- slow path (deg > 32): staged through g_ex ----
    float m0 = -FLT_MAX, m1 = -FLT_MAX, m2 = -FLT_MAX, m3 = -FLT_MAX;
    for (int e = start + l; e < end; e += 32) {
        int s = g_csr[e];
        float4 as = *(const float4*)&g_as[s * 4];
        float a0 = lrelu(as.x + ad0), a1 = lrelu(as.y + ad1);
        float a2 = lrelu(as.z + ad2), a3 = lrelu(as.w + ad3);
        *(float4*)&g_ex[e * 4] = make_float4(a0, a1, a2, a3);
        m0 = fmaxf(m0, a0); m1 = fmaxf(m1, a1);
        m2 = fmaxf(m2, a2); m3 = fmaxf(m3, a3);
    }
    #pragma unroll
    for (int off = 16; off > 0; off >>= 1) {
        m0 = fmaxf(m0, __shfl_xor_sync(0xffffffffu, m0, off));
        m1 = fmaxf(m1, __shfl_xor_sync(0xffffffffu, m1, off));
        m2 = fmaxf(m2, __shfl_xor_sync(0xffffffffu, m2, off));
        m3 = fmaxf(m3, __shfl_xor_sync(0xffffffffu, m3, off));
    }
    float d0 = 0.f, d1 = 0.f, d2 = 0.f, d3 = 0.f;
    for (int e = start + l; e < end; e += 32) {
        float4 a = *(float4*)&g_ex[e * 4];
        float e0 = expf(a.x - m0), e1 = expf(a.y - m1);
        float e2 = expf(a.z - m2), e3 = expf(a.w - m3);
        *(float4*)&g_ex[e * 4] = make_float4(e0, e1, e2, e3);
        d0 += e0; d1 += e1; d2 += e2; d3 += e3;
    }
    #pragma unroll
    for (int off = 16; off > 0; off >>= 1) {
        d0 += __shfl_xor_sync(0xffffffffu, d0, off);
        d1 += __shfl_xor_sync(0xffffffffu, d1, off);
        d2 += __shfl_xor_sync(0xffffffffu, d2, off);
        d3 += __shfl_xor_sync(0xffffffffu, d3, off);
    }
    __syncwarp();
    float den = hd == 0 ? d0 : hd == 1 ? d1 : hd == 2 ? d2 : d3;
    invden = 1.0f / den;
    float4 acc = make_float4(0.f, 0.f, 0.f, 0.f);
    for (int e = start; e < end; e++) {
        int s = g_csr[e];
        float w = g_ex[e * 4 + hd] * invden + 1.0f;
        float2 za, zb;
        ld_zh4(s, c0, za, zb);
        acc.x += w * za.x; acc.y += w * za.y;
        acc.z += w * zb.x; acc.w += w * zb.y;
    }
    float4 hv = *(const float4*)&h_in[n * DD + c0];
    float4 o;
    o.x = elu(acc.x) + hv.x;
    o.y = elu(acc.y) + hv.y;
    o.z = elu(acc.z) + hv.z;
    o.w = elu(acc.w) + hv.w;
    *(float4*)&h_out[n * DD + c0] = o;
}

// ---------------- readout (ptr sorted: run-length segment reduce) ---------
#define RNODES 64   // nodes per block

__global__ void k_r1(const void* __restrict__ ptr) {
    int c = threadIdx.x;                       // channel 0..127
    int n0 = blockIdx.x * RNODES;
    // block 0 also computes per-graph counts (binary search in sorted ptr)
    if (blockIdx.x == 0 && c < NB) {
        int b = c;
        int lo = 0, hi = NN;
        while (lo < hi) { int m = (lo + hi) >> 1; if (ld_idx(ptr, m) < b) lo = m + 1; else hi = m; }
        int lo2 = lo, hi2 = NN;
        while (lo2 < hi2) { int m = (lo2 + hi2) >> 1; if (ld_idx(ptr, m) < b + 1) lo2 = m + 1; else hi2 = m; }
        g_gcnt[b] = hi2 - lo;
    }
    int nend = n0 + RNODES; if (nend > NN) nend = NN;
    if (n0 >= NN) return;
    float acc = 0.f;
    int cur = ld_idx(ptr, n0);
    for (int n = n0; n < nend; n++) {
        int g = ld_idx(ptr, n);                // uniform across block
        if (g != cur) {
            atomicAdd(&g_gsum[cur * DD + c], acc);
            acc = 0.f; cur = g;
        }
        acc += g_hA[n * DD + c];
    }
    atomicAdd(&g_gsum[cur * DD + c], acc);
}

__global__ void k_mlp(const float* __restrict__ w0, const float* __restrict__ b0,
                      const float* __restrict__ w1, const float* __restrict__ b1,
                      float* __restrict__ out) {
    __shared__ float gv[DD];
    __shared__ float red[64];
    int b = blockIdx.x, t = threadIdx.x;
    float cnt = fmaxf((float)g_gcnt[b], 1.0f);
    gv[t]      = fmaxf(g_gsum[b * DD + t] / cnt, 0.f);
    gv[t + 64] = fmaxf(g_gsum[b * DD + t + 64] / cnt, 0.f);
    __syncthreads();
    float acc = b0[t];
    for (int k = 0; k < DD; k++) acc += gv[k] * w0[k * 64 + t];
    acc = fmaxf(acc, 0.f);
    red[t] = acc * w1[t];
    __syncthreads();
    for (int off = 32; off > 0; off >>= 1) {
        if (t < off) red[t] += red[t + off];
        __syncthreads();
    }
    if (t == 0) out[b] = red[0] + b1[0];
}

// ---------------- launch ---------------------------------------------------
extern "C" void kernel_launch(void* const* d_in, const int* in_sizes, int n_in,
                              void* d_out, int out_size) {
    const void*  edge    = d_in[1];
    const void*  ptr     = d_in[2];
    const float* emb     = (const float*)d_in[3];
    const float* lin_w   = (const float*)d_in[4];
    const float* att_src = (const float*)d_in[5];
    const float* att_dst = (const float*)d_in[6];
    const float* w0      = (const float*)d_in[7];
    const float* b0      = (const float*)d_in[8];
    const float* w1      = (const float*)d_in[9];
    const float* b1      = (const float*)d_in[10];
    float* out = (float*)d_out;

    const int NBLK_SCAN = (NN + 1023) / 1024;          // 49
    const int GE4 = (NE + 256 * EPT - 1) / (256 * EPT);  // 4 edges/thread
    const int GW  = (NN + 7) / 8;                      // warp-per-node grids (6250)
    const int GG  = (NN + 127) / 128;                  // 391 gemm blocks

    void* p_deg = nullptr; void* p_gsum = nullptr;
    cudaGetSymbolAddress(&p_deg, g_deg);
    cudaGetSymbolAddress(&p_gsum, g_gsum);

    // dtype detection + CSR build (by destination), self loop first
    k_detect<<<1, 32>>>(edge);
    cudaMemsetAsync(p_deg, 0, NN * sizeof(int));
    cudaMemsetAsync(p_gsum, 0, NB * DD * sizeof(float));
    k_count<<<GE4, 256>>>(edge);
    k_scan<<<NBLK_SCAN, 1024>>>();
    k_scatter<<<GE4, 256>>>(edge);

    // weight split + layer 1 (input rows identical -> closed form)
    k_wsplit<<<(2 * DD * DD + 255) / 256, 256>>>(lin_w);
    k_z0<<<1, 128>>>(emb, lin_w);
    k_layer1<<<GW, 256>>>(emb);

    // layer 2: hA -> hB
    k_gemm<<<GG, 256>>>(0, 0);
    k_coef<<<GW, 256>>>(att_src + 1 * DD, att_dst + 1 * DD);
    k_edge<<<GW, 256>>>(0);

    // layer 3: hB -> hA
    k_gemm<<<GG, 256>>>(1, 1);
    k_coef<<<GW, 256>>>(att_src + 2 * DD, att_dst + 2 * DD);
    k_edge<<<GW, 256>>>(1);

    // readout
    k_r1<<<(NN + RNODES - 1) / RNODES, DD>>>(ptr);
    k_mlp<<<NB, 64>>>(w0, b0, w1, b1, out);
}

// round 14
// speedup vs baseline: 1.2942x; 1.2942x over previous
#include <cuda_runtime.h>
#include <cuda_bf16.h>
#include <cuda_fp16.h>
#include <math.h>
#include <float.h>
#include <mma.h>

using namespace nvcuda;

#define NN 50000
#define NE 600000
#define NT (NE + NN)      // edges incl. one self loop per node
#define NB 128
#define DD 128
#define NEG 0.2f

// ---------------- scratch (static device globals; no runtime alloc) -------
__device__ int   g_i64;            // 1 if index inputs are int64, 0 if int32
__device__ int   g_deg[NN];
__device__ int   g_rowptr[NN + 1];
__device__ int   g_cursor[NN];
__device__ int   g_csr[NT];
__device__ int   g_bsum[64];
__device__ float g_z[(NN + 128) * DD];    // padded: gemm tiles store unguarded
__device__ __half g_zh[NN * DD];          // fp16 gather copy of z
__device__ float g_hA[NN * DD];
__device__ float g_hB[NN * DD];
__device__ float g_as[NN * 4];
__device__ float g_ad[NN * 4];
__device__ float g_ex[NT * 4];
__device__ float g_z0[DD];
__device__ float g_gsum[NB * DD];
__device__ int   g_gcnt[NB];
__device__ __nv_bfloat16 g_Whi[2 * DD * DD];
__device__ __nv_bfloat16 g_Wlo[2 * DD * DD];

__device__ __forceinline__ float lrelu(float x) { return x > 0.f ? x : NEG * x; }
__device__ __forceinline__ float elu(float x)   { return x > 0.f ? x : expm1f(x); }

// dtype-agnostic index load (branch on device flag)
__device__ __forceinline__ int ld_idx(const void* p, int i) {
    if (g_i64) return (int)((const long long*)p)[i];
    return ((const int*)p)[i];
}

// fp16 z-row gather: 8 bytes per lane (4 channels)
__device__ __forceinline__ void ld_zh4(int s, int c0, float2& za, float2& zb) {
    uint2 raw = *(const uint2*)&g_zh[s * DD + c0];
    za = __half22float2(*(__half2*)&raw.x);
    zb = __half22float2(*(__half2*)&raw.y);
}

// ---------------- dtype detection (warp ballot over 64 int64 views) ------
__global__ void k_detect(const void* edge) {
    int l = threadIdx.x;
    const long long* e64 = (const long long*)edge;
    long long v0 = e64[l];
    long long v1 = e64[32 + l];
    int bad = (v0 < 0 || v0 >= NN || v1 < 0 || v1 >= NN);
    unsigned m = __ballot_sync(0xffffffffu, bad);
    if (l == 0) g_i64 = (m == 0);   // any out-of-range 64-bit view => int32
}

// ---------------- CSR build (one edge per thread: max occupancy) ----------
__global__ void k_count(const void* __restrict__ edge) {
    int e = blockIdx.x * blockDim.x + threadIdx.x;
    if (e < NE) {
        int d = ld_idx(edge, NE + e);
        atomicAdd(&g_deg[d], 1);
    }
}

__global__ void k_s1() {                          // per-1024 block sums (deg+1)
    __shared__ int sm[256];
    int b = blockIdx.x, t = threadIdx.x;
    int base = b * 1024 + t * 4;
    int s = 0;
    #pragma unroll
    for (int j = 0; j < 4; j++) {
        int i = base + j;
        if (i < NN) s += g_deg[i] + 1;
    }
    sm[t] = s;
    __syncthreads();
    for (int off = 128; off > 0; off >>= 1) {
        if (t < off) sm[t] += sm[t + off];
        __syncthreads();
    }
    if (t == 0) g_bsum[b] = sm[0];
}

__global__ __launch_bounds__(1024)
void k_s3() {   // shuffle-based exclusive scan + setup (2 syncthreads)
    __shared__ int wsum[32];
    __shared__ int bo[64];
    int b = blockIdx.x, t = threadIdx.x;
    int lane = t & 31, w = t >> 5;
    if (t < 64) bo[t] = (t < b) ? g_bsum[t] : 0;   // gridDim.x <= 64
    int i = b * 1024 + t;
    int v = (i < NN) ? g_deg[i] + 1 : 0;
    int incl = v;
    #pragma unroll
    for (int off = 1; off < 32; off <<= 1) {
        int y = __shfl_up_sync(0xffffffffu, incl, off);
        if (lane >= off) incl += y;
    }
    if (lane == 31) wsum[w] = incl;
    __syncthreads();
    if (w == 0) {
        int x = wsum[lane];
        int sx = x;
        #pragma unroll
        for (int off = 1; off < 32; off <<= 1) {
            int y = __shfl_up_sync(0xffffffffu, sx, off);
            if (lane >= off) sx += y;
        }
        wsum[lane] = sx - x;                       // exclusive warp offsets
        int bs = bo[lane] + bo[lane + 32];
        #pragma unroll
        for (int off = 16; off > 0; off >>= 1)
            bs += __shfl_down_sync(0xffffffffu, bs, off);
        if (lane == 0) bo[0] = bs;
    }
    __syncthreads();
    incl += wsum[w];
    int boff = bo[0];
    if (i < NN) {
        int r = boff + incl - v;                   // exclusive
        g_rowptr[i] = r;
        g_csr[r] = i;                              // self loop first
        g_cursor[i] = r + 1;
        if (i == NN - 1) g_rowptr[NN] = boff + incl;
    }
}

__global__ void k_scatter(const void* __restrict__ edge) {
    int e = blockIdx.x * blockDim.x + threadIdx.x;
    if (e < NE) {
        int d = ld_idx(edge, NE + e);
        int s = ld_idx(edge, e);
        int pos = atomicAdd(&g_cursor[d], 1);
        g_csr[pos] = s;
    }
}

// ---------------- W split (bf16 hi/lo, both conv layers) ------------------
__global__ void k_wsplit(const float* __restrict__ lin_w) {
    int i = blockIdx.x * blockDim.x + threadIdx.x;
    if (i < 2 * DD * DD) {
        float w = lin_w[DD * DD + i];             // layers 1 and 2
        __nv_bfloat16 hi = __float2bfloat16_rn(w);
        g_Whi[i] = hi;
        g_Wlo[i] = __float2bfloat16_rn(w - __bfloat162float(hi));
    }
}

// ---------------- layer 1 (degenerate: all input rows identical) ----------
__global__ void k_z0(const float* __restrict__ emb, const float* __restrict__ W0) {
    int j = threadIdx.x;
    float s = 0.f;
    for (int k = 0; k < DD; k++) s += emb[k] * W0[k * DD + j];
    g_z0[j] = s;
}

__global__ void k_layer1(const float* __restrict__ emb) {
    int gid = blockIdx.x * blockDim.x + threadIdx.x;
    int n = gid >> 5;
    if (n >= NN) return;
    int c0 = (gid & 31) * 4;
    float scale = 1.0f + (float)(g_rowptr[n + 1] - g_rowptr[n]);
    float4 z = *(const float4*)&g_z0[c0];
    float4 e = *(const float4*)&emb[c0];
    float4 o;
    o.x = elu(z.x * scale) + e.x;
    o.y = elu(z.y * scale) + e.y;
    o.z = elu(z.z * scale) + e.z;
    o.w = elu(z.w * scale) + e.w;
    *(float4*)&g_hA[n * DD + c0] = o;
}

// ---------------- GEMM  z = H @ W  (split-bf16 x3, ~fp22 accuracy) --------
__global__ __launch_bounds__(256)
void k_gemm(int layer, int inB) {
    const float* __restrict__ A = inB ? g_hB : g_hA;
    const __nv_bfloat16* __restrict__ WH = g_Whi + layer * DD * DD;
    const __nv_bfloat16* __restrict__ WL = g_Wlo + layer * DD * DD;
    __shared__ __nv_bfloat16 Ahi[128][40];        // stride 40 elems = 80B (16B mult)
    __shared__ __nv_bfloat16 Alo[128][40];
    __shared__ __nv_bfloat16 Bhi[32][136];        // stride 136 elems = 272B (16B mult)
    __shared__ __nv_bfloat16 Blo[32][136];
    int tid = threadIdx.x;
    int wid = tid >> 5;
    int wr = wid >> 1;                            // 0..3 (row group of 32)
    int wc = wid & 1;                             // 0..1 (col group of 64)
    int row0 = blockIdx.x * 128;

    wmma::fragment<wmma::accumulator, 16, 16, 16, float> c[2][4];
    #pragma unroll
    for (int i = 0; i < 2; i++)
        #pragma unroll
        for (int j = 0; j < 4; j++) wmma::fill_fragment(c[i][j], 0.0f);

    for (int kt = 0; kt < 4; kt++) {
        int k0 = kt * 32;
        #pragma unroll
        for (int i = 0; i < 4; i++) {             // A tile: 128x32 fp32 -> bf16 hi/lo
            int idx = tid + i * 256;
            int r = idx >> 3, kq = idx & 7;
            float4 v = make_float4(0.f, 0.f, 0.f, 0.f);
            int gr = row0 + r;
            if (gr < NN) v = *(const float4*)&A[gr * DD + k0 + kq * 4];
            __nv_bfloat16 hx = __float2bfloat16_rn(v.x);
            __nv_bfloat16 hy = __float2bfloat16_rn(v.y);
            __nv_bfloat16 hz = __float2bfloat16_rn(v.z);
            __nv_bfloat16 hw = __float2bfloat16_rn(v.w);
            __nv_bfloat162* ph = (__nv_bfloat162*)&Ahi[r][kq * 4];
            ph[0] = __nv_bfloat162(hx, hy);
            ph[1] = __nv_bfloat162(hz, hw);
            __nv_bfloat162* pl = (__nv_bfloat162*)&Alo[r][kq * 4];
            pl[0] = __nv_bfloat162(__float2bfloat16_rn(v.x - __bfloat162float(hx)),
                                   __float2bfloat16_rn(v.y - __bfloat162float(hy)));
            pl[1] = __nv_bfloat162(__float2bfloat16_rn(v.z - __bfloat162float(hz)),
                                   __float2bfloat16_rn(v.w - __bfloat162float(hw)));
        }
        #pragma unroll
        for (int i = 0; i < 2; i++) {             // B tiles: 32x128 bf16 (presplit)
            int idx = tid + i * 256;              // 0..511
            int k = idx >> 4, q = idx & 15;       // q-th group of 8 bf16
            *(uint4*)&Bhi[k][q * 8] = *(const uint4*)&WH[(k0 + k) * DD + q * 8];
            *(uint4*)&Blo[k][q * 8] = *(const uint4*)&WL[(k0 + k) * DD + q * 8];
        }
        __syncthreads();
        #pragma unroll
        for (int ks = 0; ks < 2; ks++) {          // 2 k-steps of 16
            wmma::fragment<wmma::matrix_a, 16, 16, 16, __nv_bfloat16, wmma::row_major> ah[2], al[2];
            #pragma unroll
            for (int i = 0; i < 2; i++) {
                wmma::load_matrix_sync(ah[i], &Ahi[wr * 32 + i * 16][ks * 16], 40);
                wmma::load_matrix_sync(al[i], &Alo[wr * 32 + i * 16][ks * 16], 40);
            }
            #pragma unroll
            for (int j = 0; j < 4; j++) {
                wmma::fragment<wmma::matrix_b, 16, 16, 16, __nv_bfloat16, wmma::row_major> bh, bl;
                wmma::load_matrix_sync(bh, &Bhi[ks * 16][wc * 64 + j * 16], 136);
                wmma::load_matrix_sync(bl, &Blo[ks * 16][wc * 64 + j * 16], 136);
                #pragma unroll
                for (int i = 0; i < 2; i++) {
                    wmma::mma_sync(c[i][j], al[i], bh, c[i][j]);   // lo*hi
                    wmma::mma_sync(c[i][j], ah[i], bl, c[i][j]);   // hi*lo
                    wmma::mma_sync(c[i][j], ah[i], bh, c[i][j]);   // hi*hi
                }
            }
        }
        __syncthreads();
    }
    // store (g_z padded by 128 rows: unguarded OK)
    #pragma unroll
    for (int i = 0; i < 2; i++)
        #pragma unroll
        for (int j = 0; j < 4; j++) {
            int gr = row0 + wr * 32 + i * 16;
            int gcol = wc * 64 + j * 16;
            wmma::store_matrix_sync(&g_z[gr * DD + gcol], c[i][j], DD, wmma::mem_row_major);
        }
}

// ---------------- attention coefficients + fp16 z copy --------------------
__global__ void k_coef(const float* __restrict__ att_s, const float* __restrict__ att_d) {
    int gid = blockIdx.x * blockDim.x + threadIdx.x;
    int n = gid >> 5;
    if (n >= NN) return;
    int l = gid & 31;
    int c0 = 4 * l;
    int h = l >> 3;
    int d0 = c0 & 31;
    float4 zv = *(const float4*)&g_z[n * DD + c0];
    // fp16 gather copy (used by k_edge phase 3)
    __half2 hz0 = __floats2half2_rn(zv.x, zv.y);
    __half2 hz1 = __floats2half2_rn(zv.z, zv.w);
    uint2 raw;
    raw.x = *(unsigned*)&hz0;
    raw.y = *(unsigned*)&hz1;
    *(uint2*)&g_zh[n * DD + c0] = raw;
    const float* sv = att_s + h * 32 + d0;
    const float* dv = att_d + h * 32 + d0;
    float ps = zv.x * sv[0] + zv.y * sv[1] + zv.z * sv[2] + zv.w * sv[3];
    float pd = zv.x * dv[0] + zv.y * dv[1] + zv.z * dv[2] + zv.w * dv[3];
    #pragma unroll
    for (int off = 1; off <= 4; off <<= 1) {
        ps += __shfl_xor_sync(0xffffffffu, ps, off);
        pd += __shfl_xor_sync(0xffffffffu, pd, off);
    }
    if ((l & 7) == 0) {
        g_as[n * 4 + h] = ps;
        g_ad[n * 4 + h] = pd;
    }
}

// ---------------- fused edge softmax + aggregation + ELU + residual ------
__global__ __launch_bounds__(256)
void k_edge(int inB) {
    const float* __restrict__ h_in = inB ? g_hB : g_hA;
    float* __restrict__ h_out      = inB ? g_hA : g_hB;
    __shared__ float s_ex[8][32 * 4];             // per-warp [edge][head]
    int gid = blockIdx.x * blockDim.x + threadIdx.x;
    int n = gid >> 5;
    if (n >= NN) return;
    int l = gid & 31;
    int ww = (threadIdx.x >> 5);
    int start = g_rowptr[n], end = g_rowptr[n + 1];
    int deg = end - start;
    float ad0 = g_ad[n * 4 + 0], ad1 = g_ad[n * 4 + 1];
    float ad2 = g_ad[n * 4 + 2], ad3 = g_ad[n * 4 + 3];
    int hd = l >> 3;
    int c0 = 4 * l;
    float invden;

    if (deg <= 32) {
        // ---- fast path: one edge per lane ----
        int sidx = 0;
        float a0 = -FLT_MAX, a1 = -FLT_MAX, a2 = -FLT_MAX, a3 = -FLT_MAX;
        if (l < deg) {
            sidx = g_csr[start + l];
            float4 as = *(const float4*)&g_as[sidx * 4];
            a0 = lrelu(as.x + ad0); a1 = lrelu(as.y + ad1);
            a2 = lrelu(as.z + ad2); a3 = lrelu(as.w + ad3);
        }
        float m0 = a0, m1 = a1, m2 = a2, m3 = a3;
        #pragma unroll
        for (int off = 16; off > 0; off >>= 1) {
            m0 = fmaxf(m0, __shfl_xor_sync(0xffffffffu, m0, off));
            m1 = fmaxf(m1, __shfl_xor_sync(0xffffffffu, m1, off));
            m2 = fmaxf(m2, __shfl_xor_sync(0xffffffffu, m2, off));
            m3 = fmaxf(m3, __shfl_xor_sync(0xffffffffu, m3, off));
        }
        float e0 = 0.f, e1 = 0.f, e2 = 0.f, e3 = 0.f;
        if (l < deg) {
            e0 = expf(a0 - m0); e1 = expf(a1 - m1);
            e2 = expf(a2 - m2); e3 = expf(a3 - m3);
            *(float4*)&s_ex[ww][l * 4] = make_float4(e0, e1, e2, e3);
        }
        float d0 = e0, d1 = e1, d2 = e2, d3 = e3;
        #pragma unroll
        for (int off = 16; off > 0; off >>= 1) {
            d0 += __shfl_xor_sync(0xffffffffu, d0, off);
            d1 += __shfl_xor_sync(0xffffffffu, d1, off);
            d2 += __shfl_xor_sync(0xffffffffu, d2, off);
            d3 += __shfl_xor_sync(0xffffffffu, d3, off);
        }
        __syncwarp();
        float den = hd == 0 ? d0 : hd == 1 ? d1 : hd == 2 ? d2 : d3;
        invden = 1.0f / den;
        float4 acc = make_float4(0.f, 0.f, 0.f, 0.f);
        for (int e = 0; e < deg; e++) {
            int s = __shfl_sync(0xffffffffu, sidx, e);
            float w = s_ex[ww][e * 4 + hd] * invden + 1.0f;
            float2 za, zb;
            ld_zh4(s, c0, za, zb);
            acc.x += w * za.x; acc.y += w * za.y;
            acc.z += w * zb.x; acc.w += w * zb.y;
        }
        float4 hv = *(const float4*)&h_in[n * DD + c0];
        float4 o;
        o.x = elu(acc.x) + hv.x;
        o.y = elu(acc.y) + hv.y;
        o.z = elu(acc.z) + hv.z;
        o.w = elu(acc.w) + hv.w;
        *(float4*)&h_out[n * DD + c0] = o;
        return;
    }

    // ---- slow path (deg > 32): staged through g_ex ----
    float m0 = -FLT_MAX, m1 = -FLT_MAX, m2 = -FLT_MAX, m3 = -FLT_MAX;
    for (int e = start + l; e < end; e += 32) {
        int s = g_csr[e];
        float4 as = *(const float4*)&g_as[s * 4];
        float a0 = lrelu(as.x + ad0), a1 = lrelu(as.y + ad1);
        float a2 = lrelu(as.z + ad2), a3 = lrelu(as.w + ad3);
        *(float4*)&g_ex[e * 4] = make_float4(a0, a1, a2, a3);
        m0 = fmaxf(m0, a0); m1 = fmaxf(m1, a1);
        m2 = fmaxf(m2, a2); m3 = fmaxf(m3, a3);
    }
    #pragma unroll
    for (int off = 16; off > 0; off >>= 1) {
        m0 = fmaxf(m0, __shfl_xor_sync(0xffffffffu, m0, off));
        m1 = fmaxf(m1, __shfl_xor_sync(0xffffffffu, m1, off));
        m2 = fmaxf(m2, __shfl_xor_sync(0xffffffffu, m2, off));
        m3 = fmaxf(m3, __shfl_xor_sync(0xffffffffu, m3, off));
    }
    float d0 = 0.f, d1 = 0.f, d2 = 0.f, d3 = 0.f;
    for (int e = start + l; e < end; e += 32) {
        float4 a = *(float4*)&g_ex[e * 4];
        float e0 = expf(a.x - m0), e1 = expf(a.y - m1);
        float e2 = expf(a.z - m2), e3 = expf(a.w - m3);
        *(float4*)&g_ex[e * 4] = make_float4(e0, e1, e2, e3);
        d0 += e0; d1 += e1; d2 += e2; d3 += e3;
    }
    #pragma unroll
    for (int off = 16; off > 0; off >>= 1) {
        d0 += __shfl_xor_sync(0xffffffffu, d0, off);
        d1 += __shfl_xor_sync(0xffffffffu, d1, off);
        d2 += __shfl_xor_sync(0xffffffffu, d2, off);
        d3 += __shfl_xor_sync(0xffffffffu, d3, off);
    }
    __syncwarp();
    float den = hd == 0 ? d0 : hd == 1 ? d1 : hd == 2 ? d2 : d3;
    invden = 1.0f / den;
    float4 acc = make_float4(0.f, 0.f, 0.f, 0.f);
    for (int e = start; e < end; e++) {
        int s = g_csr[e];
        float w = g_ex[e * 4 + hd] * invden + 1.0f;
        float2 za, zb;
        ld_zh4(s, c0, za, zb);
        acc.x += w * za.x; acc.y += w * za.y;
        acc.z += w * zb.x; acc.w += w * zb.y;
    }
    float4 hv = *(const float4*)&h_in[n * DD + c0];
    float4 o;
    o.x = elu(acc.x) + hv.x;
    o.y = elu(acc.y) + hv.y;
    o.z = elu(acc.z) + hv.z;
    o.w = elu(acc.w) + hv.w;
    *(float4*)&h_out[n * DD + c0] = o;
}

// ---------------- readout (ptr sorted: run-length segment reduce) ---------
#define RNODES 64   // nodes per block

__global__ void k_r1(const void* __restrict__ ptr) {
    int c = threadIdx.x;                       // channel 0..127
    int n0 = blockIdx.x * RNODES;
    // block 0 also computes per-graph counts (binary search in sorted ptr)
    if (blockIdx.x == 0 && c < NB) {
        int b = c;
        int lo = 0, hi = NN;
        while (lo < hi) { int m = (lo + hi) >> 1; if (ld_idx(ptr, m) < b) lo = m + 1; else hi = m; }
        int lo2 = lo, hi2 = NN;
        while (lo2 < hi2) { int m = (lo2 + hi2) >> 1; if (ld_idx(ptr, m) < b + 1) lo2 = m + 1; else hi2 = m; }
        g_gcnt[b] = hi2 - lo;
    }
    int nend = n0 + RNODES; if (nend > NN) nend = NN;
    if (n0 >= NN) return;
    float acc = 0.f;
    int cur = ld_idx(ptr, n0);
    for (int n = n0; n < nend; n++) {
        int g = ld_idx(ptr, n);                // uniform across block
        if (g != cur) {
            atomicAdd(&g_gsum[cur * DD + c], acc);
            acc = 0.f; cur = g;
        }
        acc += g_hA[n * DD + c];
    }
    atomicAdd(&g_gsum[cur * DD + c], acc);
}

__global__ void k_mlp(const float* __restrict__ w0, const float* __restrict__ b0,
                      const float* __restrict__ w1, const float* __restrict__ b1,
                      float* __restrict__ out) {
    __shared__ float gv[DD];
    __shared__ float red[64];
    int b = blockIdx.x, t = threadIdx.x;
    float cnt = fmaxf((float)g_gcnt[b], 1.0f);
    gv[t]      = fmaxf(g_gsum[b * DD + t] / cnt, 0.f);
    gv[t + 64] = fmaxf(g_gsum[b * DD + t + 64] / cnt, 0.f);
    __syncthreads();
    float acc = b0[t];
    for (int k = 0; k < DD; k++) acc += gv[k] * w0[k * 64 + t];
    acc = fmaxf(acc, 0.f);
    red[t] = acc * w1[t];
    __syncthreads();
    for (int off = 32; off > 0; off >>= 1) {
        if (t < off) red[t] += red[t + off];
        __syncthreads();
    }
    if (t == 0) out[b] = red[0] + b1[0];
}

// ---------------- launch ---------------------------------------------------
extern "C" void kernel_launch(void* const* d_in, const int* in_sizes, int n_in,
                              void* d_out, int out_size) {
    const void*  edge    = d_in[1];
    const void*  ptr     = d_in[2];
    const float* emb     = (const float*)d_in[3];
    const float* lin_w   = (const float*)d_in[4];
    const float* att_src = (const float*)d_in[5];
    const float* att_dst = (const float*)d_in[6];
    const float* w0      = (const float*)d_in[7];
    const float* b0      = (const float*)d_in[8];
    const float* w1      = (const float*)d_in[9];
    const float* b1      = (const float*)d_in[10];
    float* out = (float*)d_out;

    const int NBLK_SCAN = (NN + 1023) / 1024;          // 49
    const int GE  = (NE + 255) / 256;                  // one edge per thread
    const int GW  = (NN + 7) / 8;                      // warp-per-node grids (6250)
    const int GG  = (NN + 127) / 128;                  // 391 gemm blocks

    void* p_deg = nullptr; void* p_gsum = nullptr;
    cudaGetSymbolAddress(&p_deg, g_deg);
    cudaGetSymbolAddress(&p_gsum, g_gsum);

    // dtype detection + CSR build (by destination), self loop first
    k_detect<<<1, 32>>>(edge);
    cudaMemsetAsync(p_deg, 0, NN * sizeof(int));
    cudaMemsetAsync(p_gsum, 0, NB * DD * sizeof(float));
    k_count<<<GE, 256>>>(edge);
    k_s1<<<NBLK_SCAN, 256>>>();
    k_s3<<<NBLK_SCAN, 1024>>>();
    k_scatter<<<GE, 256>>>(edge);

    // weight split + layer 1 (input rows identical -> closed form)
    k_wsplit<<<(2 * DD * DD + 255) / 256, 256>>>(lin_w);
    k_z0<<<1, 128>>>(emb, lin_w);
    k_layer1<<<GW, 256>>>(emb);

    // layer 2: hA -> hB
    k_gemm<<<GG, 256>>>(0, 0);
    k_coef<<<GW, 256>>>(att_src + 1 * DD, att_dst + 1 * DD);
    k_edge<<<GW, 256>>>(0);

    // layer 3: hB -> hA
    k_gemm<<<GG, 256>>>(1, 1);
    k_coef<<<GW, 256>>>(att_src + 2 * DD, att_dst + 2 * DD);
    k_edge<<<GW, 256>>>(1);

    // readout
    k_r1<<<(NN + RNODES - 1) / RNODES, DD>>>(ptr);
    k_mlp<<<NB, 64>>>(w0, b0, w1, b1, out);
}

// round 15
// speedup vs baseline: 1.4765x; 1.1408x over previous
#include <cuda_runtime.h>
#include <cuda_bf16.h>
#include <cuda_fp16.h>
#include <math.h>
#include <float.h>
#include <mma.h>

using namespace nvcuda;

#define NN 50000
#define NE 600000
#define NT (NE + NN)      // edges incl. one self loop per node
#define NB 128
#define DD 128
#define NEG 0.2f

// ---------------- scratch (static device globals; no runtime alloc) -------
__device__ int   g_i64;            // 1 if index inputs are int64, 0 if int32
__device__ int   g_deg[NN];
__device__ int   g_rowptr[NN + 1];
__device__ int   g_cursor[NN];
__device__ int   g_csr[NT];
__device__ int   g_bsum[64];
__device__ float g_z[(NN + 128) * DD];    // padded: gemm tiles store unguarded
__device__ __half g_zh[NN * DD];          // fp16 gather copy of z
__device__ float g_hA[NN * DD];
__device__ float g_hB[NN * DD];
__device__ float g_as[NN * 4];
__device__ float g_ad[NN * 4];
__device__ float g_ex[NT * 4];
__device__ float g_z0[DD];
__device__ float g_gsum[NB * DD];
__device__ int   g_gcnt[NB];
__device__ __nv_bfloat16 g_Whi[2 * DD * DD];
__device__ __nv_bfloat16 g_Wlo[2 * DD * DD];

__device__ __forceinline__ float lrelu(float x) { return x > 0.f ? x : NEG * x; }
__device__ __forceinline__ float elu(float x)   { return x > 0.f ? x : expm1f(x); }

// dtype-agnostic index load (branch on device flag)
__device__ __forceinline__ int ld_idx(const void* p, int i) {
    if (g_i64) return (int)((const long long*)p)[i];
    return ((const int*)p)[i];
}

// fp16 z-row gather: 8 bytes per lane (4 channels)
__device__ __forceinline__ void ld_zh4(int s, int c0, float2& za, float2& zb) {
    uint2 raw = *(const uint2*)&g_zh[s * DD + c0];
    za = __half22float2(*(__half2*)&raw.x);
    zb = __half22float2(*(__half2*)&raw.y);
}

// ---------------- dtype detection (warp ballot over 64 int64 views) ------
__global__ void k_detect(const void* edge) {
    int l = threadIdx.x;
    const long long* e64 = (const long long*)edge;
    long long v0 = e64[l];
    long long v1 = e64[32 + l];
    int bad = (v0 < 0 || v0 >= NN || v1 < 0 || v1 >= NN);
    unsigned m = __ballot_sync(0xffffffffu, bad);
    if (l == 0) g_i64 = (m == 0);   // any out-of-range 64-bit view => int32
}

// ---------------- CSR build (one edge per thread: max occupancy) ----------
__global__ void k_count(const void* __restrict__ edge) {
    int e = blockIdx.x * blockDim.x + threadIdx.x;
    if (e < NE) {
        int d = ld_idx(edge, NE + e);
        atomicAdd(&g_deg[d], 1);
    }
}

__global__ void k_s1() {                          // per-1024 block sums (deg+1)
    __shared__ int sm[256];
    int b = blockIdx.x, t = threadIdx.x;
    int base = b * 1024 + t * 4;
    int s = 0;
    #pragma unroll
    for (int j = 0; j < 4; j++) {
        int i = base + j;
        if (i < NN) s += g_deg[i] + 1;
    }
    sm[t] = s;
    __syncthreads();
    for (int off = 128; off > 0; off >>= 1) {
        if (t < off) sm[t] += sm[t + off];
        __syncthreads();
    }
    if (t == 0) g_bsum[b] = sm[0];
}

__global__ __launch_bounds__(1024)
void k_s3() {   // shuffle-based exclusive scan + setup (2 syncthreads)
    __shared__ int wsum[32];
    __shared__ int bo[64];
    int b = blockIdx.x, t = threadIdx.x;
    int lane = t & 31, w = t >> 5;
    if (t < 64) bo[t] = (t < b) ? g_bsum[t] : 0;   // gridDim.x <= 64
    int i = b * 1024 + t;
    int v = (i < NN) ? g_deg[i] + 1 : 0;
    int incl = v;
    #pragma unroll
    for (int off = 1; off < 32; off <<= 1) {
        int y = __shfl_up_sync(0xffffffffu, incl, off);
        if (lane >= off) incl += y;
    }
    if (lane == 31) wsum[w] = incl;
    __syncthreads();
    if (w == 0) {
        int x = wsum[lane];
        int sx = x;
        #pragma unroll
        for (int off = 1; off < 32; off <<= 1) {
            int y = __shfl_up_sync(0xffffffffu, sx, off);
            if (lane >= off) sx += y;
        }
        wsum[lane] = sx - x;                       // exclusive warp offsets
        int bs = bo[lane] + bo[lane + 32];
        #pragma unroll
        for (int off = 16; off > 0; off >>= 1)
            bs += __shfl_down_sync(0xffffffffu, bs, off);
        if (lane == 0) bo[0] = bs;
    }
    __syncthreads();
    incl += wsum[w];
    int boff = bo[0];
    if (i < NN) {
        int r = boff + incl - v;                   // exclusive
        g_rowptr[i] = r;
        g_csr[r] = i;                              // self loop first
        g_cursor[i] = r + 1;
        if (i == NN - 1) g_rowptr[NN] = boff + incl;
    }
}

__global__ void k_scatter(const void* __restrict__ edge) {
    int e = blockIdx.x * blockDim.x + threadIdx.x;
    if (e < NE) {
        int d = ld_idx(edge, NE + e);
        int s = ld_idx(edge, e);
        int pos = atomicAdd(&g_cursor[d], 1);
        g_csr[pos] = s;
    }
}

// ---------------- W split (bf16 hi/lo, both conv layers) ------------------
__global__ void k_wsplit(const float* __restrict__ lin_w) {
    int i = blockIdx.x * blockDim.x + threadIdx.x;
    if (i < 2 * DD * DD) {
        float w = lin_w[DD * DD + i];             // layers 1 and 2
        __nv_bfloat16 hi = __float2bfloat16_rn(w);
        g_Whi[i] = hi;
        g_Wlo[i] = __float2bfloat16_rn(w - __bfloat162float(hi));
    }
}

// ---------------- layer 1 (degenerate: all input rows identical) ----------
__global__ void k_z0(const float* __restrict__ emb, const float* __restrict__ W0) {
    int j = threadIdx.x;
    float s = 0.f;
    for (int k = 0; k < DD; k++) s += emb[k] * W0[k * DD + j];
    g_z0[j] = s;
}

// depends only on g_deg (not rowptr): scale = 1 + (deg + 1) = deg + 2
__global__ void k_layer1(const float* __restrict__ emb) {
    int gid = blockIdx.x * blockDim.x + threadIdx.x;
    int n = gid >> 5;
    if (n >= NN) return;
    int c0 = (gid & 31) * 4;
    float scale = (float)(g_deg[n] + 2);
    float4 z = *(const float4*)&g_z0[c0];
    float4 e = *(const float4*)&emb[c0];
    float4 o;
    o.x = elu(z.x * scale) + e.x;
    o.y = elu(z.y * scale) + e.y;
    o.z = elu(z.z * scale) + e.z;
    o.w = elu(z.w * scale) + e.w;
    *(float4*)&g_hA[n * DD + c0] = o;
}

// ---------------- GEMM  z = H @ W  (split-bf16 x3, ~fp22 accuracy) --------
__global__ __launch_bounds__(256)
void k_gemm(int layer, int inB) {
    const float* __restrict__ A = inB ? g_hB : g_hA;
    const __nv_bfloat16* __restrict__ WH = g_Whi + layer * DD * DD;
    const __nv_bfloat16* __restrict__ WL = g_Wlo + layer * DD * DD;
    __shared__ __nv_bfloat16 Ahi[128][40];        // stride 40 elems = 80B (16B mult)
    __shared__ __nv_bfloat16 Alo[128][40];
    __shared__ __nv_bfloat16 Bhi[32][136];        // stride 136 elems = 272B (16B mult)
    __shared__ __nv_bfloat16 Blo[32][136];
    int tid = threadIdx.x;
    int wid = tid >> 5;
    int wr = wid >> 1;                            // 0..3 (row group of 32)
    int wc = wid & 1;                             // 0..1 (col group of 64)
    int row0 = blockIdx.x * 128;

    wmma::fragment<wmma::accumulator, 16, 16, 16, float> c[2][4];
    #pragma unroll
    for (int i = 0; i < 2; i++)
        #pragma unroll
        for (int j = 0; j < 4; j++) wmma::fill_fragment(c[i][j], 0.0f);

    for (int kt = 0; kt < 4; kt++) {
        int k0 = kt * 32;
        #pragma unroll
        for (int i = 0; i < 4; i++) {             // A tile: 128x32 fp32 -> bf16 hi/lo
            int idx = tid + i * 256;
            int r = idx >> 3, kq = idx & 7;
            float4 v = make_float4(0.f, 0.f, 0.f, 0.f);
            int gr = row0 + r;
            if (gr < NN) v = *(const float4*)&A[gr * DD + k0 + kq * 4];
            __nv_bfloat16 hx = __float2bfloat16_rn(v.x);
            __nv_bfloat16 hy = __float2bfloat16_rn(v.y);
            __nv_bfloat16 hz = __float2bfloat16_rn(v.z);
            __nv_bfloat16 hw = __float2bfloat16_rn(v.w);
            __nv_bfloat162* ph = (__nv_bfloat162*)&Ahi[r][kq * 4];
            ph[0] = __nv_bfloat162(hx, hy);
            ph[1] = __nv_bfloat162(hz, hw);
            __nv_bfloat162* pl = (__nv_bfloat162*)&Alo[r][kq * 4];
            pl[0] = __nv_bfloat162(__float2bfloat16_rn(v.x - __bfloat162float(hx)),
                                   __float2bfloat16_rn(v.y - __bfloat162float(hy)));
            pl[1] = __nv_bfloat162(__float2bfloat16_rn(v.z - __bfloat162float(hz)),
                                   __float2bfloat16_rn(v.w - __bfloat162float(hw)));
        }
        #pragma unroll
        for (int i = 0; i < 2; i++) {             // B tiles: 32x128 bf16 (presplit)
            int idx = tid + i * 256;              // 0..511
            int k = idx >> 4, q = idx & 15;       // q-th group of 8 bf16
            *(uint4*)&Bhi[k][q * 8] = *(const uint4*)&WH[(k0 + k) * DD + q * 8];
            *(uint4*)&Blo[k][q * 8] = *(const uint4*)&WL[(k0 + k) * DD + q * 8];
        }
        __syncthreads();
        #pragma unroll
        for (int ks = 0; ks < 2; ks++) {          // 2 k-steps of 16
            wmma::fragment<wmma::matrix_a, 16, 16, 16, __nv_bfloat16, wmma::row_major> ah[2], al[2];
            #pragma unroll
            for (int i = 0; i < 2; i++) {
                wmma::load_matrix_sync(ah[i], &Ahi[wr * 32 + i * 16][ks * 16], 40);
                wmma::load_matrix_sync(al[i], &Alo[wr * 32 + i * 16][ks * 16], 40);
            }
            #pragma unroll
            for (int j = 0; j < 4; j++) {
                wmma::fragment<wmma::matrix_b, 16, 16, 16, __nv_bfloat16, wmma::row_major> bh, bl;
                wmma::load_matrix_sync(bh, &Bhi[ks * 16][wc * 64 + j * 16], 136);
                wmma::load_matrix_sync(bl, &Blo[ks * 16][wc * 64 + j * 16], 136);
                #pragma unroll
                for (int i = 0; i < 2; i++) {
                    wmma::mma_sync(c[i][j], al[i], bh, c[i][j]);   // lo*hi
                    wmma::mma_sync(c[i][j], ah[i], bl, c[i][j]);   // hi*lo
                    wmma::mma_sync(c[i][j], ah[i], bh, c[i][j]);   // hi*hi
                }
            }
        }
        __syncthreads();
    }
    // store (g_z padded by 128 rows: unguarded OK)
    #pragma unroll
    for (int i = 0; i < 2; i++)
        #pragma unroll
        for (int j = 0; j < 4; j++) {
            int gr = row0 + wr * 32 + i * 16;
            int gcol = wc * 64 + j * 16;
            wmma::store_matrix_sync(&g_z[gr * DD + gcol], c[i][j], DD, wmma::mem_row_major);
        }
}

// ---------------- attention coefficients + fp16 z copy --------------------
__global__ void k_coef(const float* __restrict__ att_s, const float* __restrict__ att_d) {
    int gid = blockIdx.x * blockDim.x + threadIdx.x;
    int n = gid >> 5;
    if (n >= NN) return;
    int l = gid & 31;
    int c0 = 4 * l;
    int h = l >> 3;
    int d0 = c0 & 31;
    float4 zv = *(const float4*)&g_z[n * DD + c0];
    // fp16 gather copy (used by k_edge phase 3)
    __half2 hz0 = __floats2half2_rn(zv.x, zv.y);
    __half2 hz1 = __floats2half2_rn(zv.z, zv.w);
    uint2 raw;
    raw.x = *(unsigned*)&hz0;
    raw.y = *(unsigned*)&hz1;
    *(uint2*)&g_zh[n * DD + c0] = raw;
    const float* sv = att_s + h * 32 + d0;
    const float* dv = att_d + h * 32 + d0;
    float ps = zv.x * sv[0] + zv.y * sv[1] + zv.z * sv[2] + zv.w * sv[3];
    float pd = zv.x * dv[0] + zv.y * dv[1] + zv.z * dv[2] + zv.w * dv[3];
    #pragma unroll
    for (int off = 1; off <= 4; off <<= 1) {
        ps += __shfl_xor_sync(0xffffffffu, ps, off);
        pd += __shfl_xor_sync(0xffffffffu, pd, off);
    }
    if ((l & 7) == 0) {
        g_as[n * 4 + h] = ps;
        g_ad[n * 4 + h] = pd;
    }
}

// ---------------- fused edge softmax + aggregation + ELU + residual ------
__global__ __launch_bounds__(256)
void k_edge(int inB) {
    const float* __restrict__ h_in = inB ? g_hB : g_hA;
    float* __restrict__ h_out      = inB ? g_hA : g_hB;
    __shared__ float s_ex[8][32 * 4];             // per-warp [edge][head]
    int gid = blockIdx.x * blockDim.x + threadIdx.x;
    int n = gid >> 5;
    if (n >= NN) return;
    int l = gid & 31;
    int ww = (threadIdx.x >> 5);
    int start = g_rowptr[n], end = g_rowptr[n + 1];
    int deg = end - start;
    float ad0 = g_ad[n * 4 + 0], ad1 = g_ad[n * 4 + 1];
    float ad2 = g_ad[n * 4 + 2], ad3 = g_ad[n * 4 + 3];
    int hd = l >> 3;
    int c0 = 4 * l;
    float invden;

    if (deg <= 32) {
        // ---- fast path: one edge per lane ----
        int sidx = 0;
        float a0 = -FLT_MAX, a1 = -FLT_MAX, a2 = -FLT_MAX, a3 = -FLT_MAX;
        if (l < deg) {
            sidx = g_csr[start + l];
            float4 as = *(const float4*)&g_as[sidx * 4];
            a0 = lrelu(as.x + ad0); a1 = lrelu(as.y + ad1);
            a2 = lrelu(as.z + ad2); a3 = lrelu(as.w + ad3);
        }
        float m0 = a0, m1 = a1, m2 = a2, m3 = a3;
        #pragma unroll
        for (int off = 16; off > 0; off >>= 1) {
            m0 = fmaxf(m0, __shfl_xor_sync(0xffffffffu, m0, off));
            m1 = fmaxf(m1, __shfl_xor_sync(0xffffffffu, m1, off));
            m2 = fmaxf(m2, __shfl_xor_sync(0xffffffffu, m2, off));
            m3 = fmaxf(m3, __shfl_xor_sync(0xffffffffu, m3, off));
        }
        float e0 = 0.f, e1 = 0.f, e2 = 0.f, e3 = 0.f;
        if (l < deg) {
            e0 = expf(a0 - m0); e1 = expf(a1 - m1);
            e2 = expf(a2 - m2); e3 = expf(a3 - m3);
            *(float4*)&s_ex[ww][l * 4] = make_float4(e0, e1, e2, e3);
        }
        float d0 = e0, d1 = e1, d2 = e2, d3 = e3;
        #pragma unroll
        for (int off = 16; off > 0; off >>= 1) {
            d0 += __shfl_xor_sync(0xffffffffu, d0, off);
            d1 += __shfl_xor_sync(0xffffffffu, d1, off);
            d2 += __shfl_xor_sync(0xffffffffu, d2, off);
            d3 += __shfl_xor_sync(0xffffffffu, d3, off);
        }
        __syncwarp();
        float den = hd == 0 ? d0 : hd == 1 ? d1 : hd == 2 ? d2 : d3;
        invden = 1.0f / den;
        float4 acc = make_float4(0.f, 0.f, 0.f, 0.f);
        for (int e = 0; e < deg; e++) {
            int s = __shfl_sync(0xffffffffu, sidx, e);
            float w = s_ex[ww][e * 4 + hd] * invden + 1.0f;
            float2 za, zb;
            ld_zh4(s, c0, za, zb);
            acc.x += w * za.x; acc.y += w * za.y;
            acc.z += w * zb.x; acc.w += w * zb.y;
        }
        float4 hv = *(const float4*)&h_in[n * DD + c0];
        float4 o;
        o.x = elu(acc.x) + hv.x;
        o.y = elu(acc.y) + hv.y;
        o.z = elu(acc.z) + hv.z;
        o.w = elu(acc.w) + hv.w;
        *(float4*)&h_out[n * DD + c0] = o;
        return;
    }

    // ---- slow path (deg > 32): staged through g_ex ----
    float m0 = -FLT_MAX, m1 = -FLT_MAX, m2 = -FLT_MAX, m3 = -FLT_MAX;
    for (int e = start + l; e < end; e += 32) {
        int s = g_csr[e];
        float4 as = *(const float4*)&g_as[s * 4];
        float a0 = lrelu(as.x + ad0), a1 = lrelu(as.y + ad1);
        float a2 = lrelu(as.z + ad2), a3 = lrelu(as.w + ad3);
        *(float4*)&g_ex[e * 4] = make_float4(a0, a1, a2, a3);
        m0 = fmaxf(m0, a0); m1 = fmaxf(m1, a1);
        m2 = fmaxf(m2, a2); m3 = fmaxf(m3, a3);
    }
    #pragma unroll
    for (int off = 16; off > 0; off >>= 1) {
        m0 = fmaxf(m0, __shfl_xor_sync(0xffffffffu, m0, off));
        m1 = fmaxf(m1, __shfl_xor_sync(0xffffffffu, m1, off));
        m2 = fmaxf(m2, __shfl_xor_sync(0xffffffffu, m2, off));
        m3 = fmaxf(m3, __shfl_xor_sync(0xffffffffu, m3, off));
    }
    float d0 = 0.f, d1 = 0.f, d2 = 0.f, d3 = 0.f;
    for (int e = start + l; e < end; e += 32) {
        float4 a = *(float4*)&g_ex[e * 4];
        float e0 = expf(a.x - m0), e1 = expf(a.y - m1);
        float e2 = expf(a.z - m2), e3 = expf(a.w - m3);
        *(float4*)&g_ex[e * 4] = make_float4(e0, e1, e2, e3);
        d0 += e0; d1 += e1; d2 += e2; d3 += e3;
    }
    #pragma unroll
    for (int off = 16; off > 0; off >>= 1) {
        d0 += __shfl_xor_sync(0xffffffffu, d0, off);
        d1 += __shfl_xor_sync(0xffffffffu, d1, off);
        d2 += __shfl_xor_sync(0xffffffffu, d2, off);
        d3 += __shfl_xor_sync(0xffffffffu, d3, off);
    }
    __syncwarp();
    float den = hd == 0 ? d0 : hd == 1 ? d1 : hd == 2 ? d2 : d3;
    invden = 1.0f / den;
    float4 acc = make_float4(0.f, 0.f, 0.f, 0.f);
    for (int e = start; e < end; e++) {
        int s = g_csr[e];
        float w = g_ex[e * 4 + hd] * invden + 1.0f;
        float2 za, zb;
        ld_zh4(s, c0, za, zb);
        acc.x += w * za.x; acc.y += w * za.y;
        acc.z += w * zb.x; acc.w += w * zb.y;
    }
    float4 hv = *(const float4*)&h_in[n * DD + c0];
    float4 o;
    o.x = elu(acc.x) + hv.x;
    o.y = elu(acc.y) + hv.y;
    o.z = elu(acc.z) + hv.z;
    o.w = elu(acc.w) + hv.w;
    *(float4*)&h_out[n * DD + c0] = o;
}

// ---------------- readout (ptr sorted: run-length segment reduce) ---------
#define RNODES 64   // nodes per block

__global__ void k_r1(const void* __restrict__ ptr) {
    int c = threadIdx.x;                       // channel 0..127
    int n0 = blockIdx.x * RNODES;
    // block 0 also computes per-graph counts (binary search in sorted ptr)
    if (blockIdx.x == 0 && c < NB) {
        int b = c;
        int lo = 0, hi = NN;
        while (lo < hi) { int m = (lo + hi) >> 1; if (ld_idx(ptr, m) < b) lo = m + 1; else hi = m; }
        int lo2 = lo, hi2 = NN;
        while (lo2 < hi2) { int m = (lo2 + hi2) >> 1; if (ld_idx(ptr, m) < b + 1) lo2 = m + 1; else hi2 = m; }
        g_gcnt[b] = hi2 - lo;
    }
    int nend = n0 + RNODES; if (nend > NN) nend = NN;
    if (n0 >= NN) return;
    float acc = 0.f;
    int cur = ld_idx(ptr, n0);
    for (int n = n0; n < nend; n++) {
        int g = ld_idx(ptr, n);                // uniform across block
        if (g != cur) {
            atomicAdd(&g_gsum[cur * DD + c], acc);
            acc = 0.f; cur = g;
        }
        acc += g_hA[n * DD + c];
    }
    atomicAdd(&g_gsum[cur * DD + c], acc);
}

__global__ void k_mlp(const float* __restrict__ w0, const float* __restrict__ b0,
                      const float* __restrict__ w1, const float* __restrict__ b1,
                      float* __restrict__ out) {
    __shared__ float gv[DD];
    __shared__ float red[64];
    int b = blockIdx.x, t = threadIdx.x;
    float cnt = fmaxf((float)g_gcnt[b], 1.0f);
    gv[t]      = fmaxf(g_gsum[b * DD + t] / cnt, 0.f);
    gv[t + 64] = fmaxf(g_gsum[b * DD + t + 64] / cnt, 0.f);
    __syncthreads();
    float acc = b0[t];
    for (int k = 0; k < DD; k++) acc += gv[k] * w0[k * 64 + t];
    acc = fmaxf(acc, 0.f);
    red[t] = acc * w1[t];
    __syncthreads();
    for (int off = 32; off > 0; off >>= 1) {
        if (t < off) red[t] += red[t + off];
        __syncthreads();
    }
    if (t == 0) out[b] = red[0] + b1[0];
}

// ---------------- launch ---------------------------------------------------
extern "C" void kernel_launch(void* const* d_in, const int* in_sizes, int n_in,
                              void* d_out, int out_size) {
    const void*  edge    = d_in[1];
    const void*  ptr     = d_in[2];
    const float* emb     = (const float*)d_in[3];
    const float* lin_w   = (const float*)d_in[4];
    const float* att_src = (const float*)d_in[5];
    const float* att_dst = (const float*)d_in[6];
    const float* w0      = (const float*)d_in[7];
    const float* b0      = (const float*)d_in[8];
    const float* w1      = (const float*)d_in[9];
    const float* b1      = (const float*)d_in[10];
    float* out = (float*)d_out;

    const int NBLK_SCAN = (NN + 1023) / 1024;          // 49
    const int GE  = (NE + 255) / 256;                  // one edge per thread
    const int GW  = (NN + 7) / 8;                      // warp-per-node grids (6250)
    const int GG  = (NN + 127) / 128;                  // 391 gemm blocks

    void* p_deg = nullptr; void* p_gsum = nullptr;
    cudaGetSymbolAddress(&p_deg, g_deg);
    cudaGetSymbolAddress(&p_gsum, g_gsum);

    // side stream + fork/join events (host objects, created once; the
    // captured op sequence is identical on every call)
    static cudaStream_t s2 = nullptr;
    static cudaEvent_t ev0 = nullptr, evA = nullptr, evB = nullptr;
    if (s2 == nullptr) {
        cudaStreamCreateWithFlags(&s2, cudaStreamNonBlocking);
        cudaEventCreateWithFlags(&ev0, cudaEventDisableTiming);
        cudaEventCreateWithFlags(&evA, cudaEventDisableTiming);
        cudaEventCreateWithFlags(&evB, cudaEventDisableTiming);
    }

    // ---- main stream: dtype detect + zeroing + degree count ----
    k_detect<<<1, 32>>>(edge);
    cudaMemsetAsync(p_deg, 0, NN * sizeof(int));
    cudaMemsetAsync(p_gsum, 0, NB * DD * sizeof(float));
    cudaEventRecord(ev0, 0);                     // fork point (pre-count)

    // side stream: weight split + z0 (independent of graph structure)
    cudaStreamWaitEvent(s2, ev0, 0);
    k_wsplit<<<(2 * DD * DD + 255) / 256, 256, 0, s2>>>(lin_w);
    k_z0<<<1, 128, 0, s2>>>(emb, lin_w);

    k_count<<<GE, 256>>>(edge);                  // main stream
    cudaEventRecord(evA, 0);                     // g_deg ready

    // side stream: layer1 (needs only g_deg) -> gemm layer2 -> coef
    cudaStreamWaitEvent(s2, evA, 0);
    k_layer1<<<GW, 256, 0, s2>>>(emb);
    k_gemm<<<GG, 256, 0, s2>>>(0, 0);
    k_coef<<<GW, 256, 0, s2>>>(att_src + 1 * DD, att_dst + 1 * DD);
    cudaEventRecord(evB, s2);

    // main stream: scan + scatter (overlaps with side-stream dense chain)
    k_s1<<<NBLK_SCAN, 256>>>();
    k_s3<<<NBLK_SCAN, 1024>>>();
    k_scatter<<<GE, 256>>>(edge);

    // join: edge needs CSR (main) + z/coef (side)
    cudaStreamWaitEvent(0, evB, 0);
    k_edge<<<GW, 256>>>(0);

    // layer 3: hB -> hA (serial on main stream)
    k_gemm<<<GG, 256>>>(1, 1);
    k_coef<<<GW, 256>>>(att_src + 2 * DD, att_dst + 2 * DD);
    k_edge<<<GW, 256>>>(1);

    // readout
    k_r1<<<(NN + RNODES - 1) / RNODES, DD>>>(ptr);
    k_mlp<<<NB, 64>>>(w0, b0, w1, b1, out);
}